// round 1
// baseline (speedup 1.0000x reference)
#include <cuda_runtime.h>
#include <math.h>

// Problem constants
#define NB   2
#define CH   128
#define HW   4096      // 64*64
#define NHD  4
#define DH   32
#define GRP  16
#define CPG  8         // channels per group
#define EPSF 1e-5f
#define ASCALE 0.42044820762685725f   // 32^(-1/4)

// Scratch (device globals: allocation-free rule)
__device__ __align__(16) float g_xn[NB*CH*HW];   // groupnorm1 output [n][c][p]
__device__ __align__(16) float g_qT[NB*CH*HW];   // q, scaled, [n][h*32+j][p]
__device__ __align__(16) float g_kT[NB*CH*HW];   // k, scaled, [n][h*32+j][p]
__device__ __align__(16) float g_v [NB*CH*HW];   // v, [n*4+h][p][j]
__device__ __align__(16) float g_o [NB*CH*HW];   // attn out, [n][h*32+j][p]
__device__ __align__(16) float g_pj[NB*CH*HW];   // out projection [n][d][p]

// ---------------------------------------------------------------------------
// GroupNorm 1: one block per (n, group); group = contiguous 32768-float slab
// ---------------------------------------------------------------------------
__global__ __launch_bounds__(512) void gn1_kernel(const float* __restrict__ x,
                                                  const float* __restrict__ sc,
                                                  const float* __restrict__ off) {
    int b = blockIdx.x;            // 0..31
    int n = b >> 4, g = b & 15;
    const int M = CPG * HW;        // 32768
    size_t base = ((size_t)n * CH + (size_t)g * CPG) * HW;
    const float* xp = x + base;

    float s = 0.f, q = 0.f;
    for (int i = threadIdx.x; i < M; i += 512) {
        float v = xp[i]; s += v; q += v * v;
    }
    __shared__ float ss[512], sq[512];
    ss[threadIdx.x] = s; sq[threadIdx.x] = q;
    __syncthreads();
    for (int st = 256; st > 0; st >>= 1) {
        if (threadIdx.x < st) {
            ss[threadIdx.x] += ss[threadIdx.x + st];
            sq[threadIdx.x] += sq[threadIdx.x + st];
        }
        __syncthreads();
    }
    float mu  = ss[0] / (float)M;
    float var = sq[0] / (float)M - mu * mu;
    float r   = rsqrtf(var + EPSF);

    for (int i = threadIdx.x; i < M; i += 512) {
        int c = g * CPG + (i >> 12);
        g_xn[base + i] = (xp[i] - mu) * r * sc[c] + off[c];
    }
}

// ---------------------------------------------------------------------------
// QKV GEMM: out[n][d][p] = sum_c xn[n][c][p] * w[c][d] + b[d]
// Tiles: 64(d) x 64(p), K chunks of 16. 256 threads, 4x4 micro-tile.
// Epilogue routes q/k (scaled, transposed layout) and v.
// ---------------------------------------------------------------------------
__global__ __launch_bounds__(256) void qkv_kernel(const float* __restrict__ w,
                                                  const float* __restrict__ bias) {
    int p0 = blockIdx.x * 64, d0 = blockIdx.y * 64, n = blockIdx.z;
    int tid = threadIdx.x, ty = tid >> 4, tx = tid & 15;
    __shared__ float Ws[16][64];
    __shared__ float Xs[16][64];
    float acc[4][4] = {};
    const float* xb = g_xn + (size_t)n * CH * HW;

    int lr = tid >> 4, lc = (tid & 15) << 2;     // load coords (1 float4 each)
    for (int c0 = 0; c0 < CH; c0 += 16) {
        *(float4*)&Ws[lr][lc] = *(const float4*)&w [(size_t)(c0 + lr) * 384 + d0 + lc];
        *(float4*)&Xs[lr][lc] = *(const float4*)&xb[(size_t)(c0 + lr) * HW  + p0 + lc];
        __syncthreads();
        #pragma unroll
        for (int k = 0; k < 16; k++) {
            float4 A = *(float4*)&Ws[k][ty * 4];
            float4 B = *(float4*)&Xs[k][tx * 4];
            float a[4] = {A.x, A.y, A.z, A.w};
            float bb[4] = {B.x, B.y, B.z, B.w};
            #pragma unroll
            for (int i = 0; i < 4; i++)
                #pragma unroll
                for (int j = 0; j < 4; j++)
                    acc[i][j] = fmaf(a[i], bb[j], acc[i][j]);
        }
        __syncthreads();
    }
    #pragma unroll
    for (int i = 0; i < 4; i++) {
        int d = d0 + ty * 4 + i;
        float bv = bias[d];
        #pragma unroll
        for (int j = 0; j < 4; j++) {
            int p = p0 + tx * 4 + j;
            float v = acc[i][j] + bv;
            if (d < 128) {
                g_qT[((size_t)n * CH + d) * HW + p] = v * ASCALE;
            } else if (d < 256) {
                g_kT[((size_t)n * CH + (d - 128)) * HW + p] = v * ASCALE;
            } else {
                int dd = d - 256, h = dd >> 5, jj = dd & 31;
                g_v[(((size_t)n * NHD + h) * HW + p) * DH + jj] = v;
            }
        }
    }
}

// ---------------------------------------------------------------------------
// Flash attention: one block = 64 query rows of one (n, head).
// 256 threads (16x16). S micro-tile 4x4, O micro-tile 4 rows x 2 dims.
// ---------------------------------------------------------------------------
__global__ __launch_bounds__(256) void attn_kernel() {
    int nh = blockIdx.y;                 // 0..7
    int n = nh >> 2, h = nh & 3;
    int q0 = blockIdx.x * 64;
    int tid = threadIdx.x, ty = tid >> 4, tx = tid & 15;

    __shared__ float Qt[32][64];         // [d][row]
    __shared__ float Kt[32][64];         // [d][key]
    __shared__ float Vs[64][32];         // [key][d]
    __shared__ float Ps[64][68];         // [row][key], padded stride 68

    const float* qsrc = g_qT + ((size_t)n * CH + h * DH) * HW;
    const float* ksrc = g_kT + ((size_t)n * CH + h * DH) * HW;
    const float* vsrc = g_v  + (size_t)nh * HW * DH;

    // Load Q tile (2048 floats = 512 float4)
    for (int f = tid; f < 512; f += 256) {
        int d = f >> 4, i4 = (f & 15) << 2;
        *(float4*)&Qt[d][i4] = *(const float4*)&qsrc[(size_t)d * HW + q0 + i4];
    }

    float m[4], l[4], O[4][2];
    #pragma unroll
    for (int i = 0; i < 4; i++) { m[i] = -1e30f; l[i] = 0.f; O[i][0] = 0.f; O[i][1] = 0.f; }

    for (int kt = 0; kt < 64; kt++) {
        int k0 = kt * 64;
        __syncthreads();   // previous PV done; Qt load visible on first iter
        for (int f = tid; f < 512; f += 256) {
            int d = f >> 4, i4 = (f & 15) << 2;
            *(float4*)&Kt[d][i4] = *(const float4*)&ksrc[(size_t)d * HW + k0 + i4];
        }
        for (int f = tid; f < 512; f += 256) {
            ((float4*)&Vs[0][0])[f] = ((const float4*)&vsrc[(size_t)k0 * DH])[f];
        }
        __syncthreads();

        // S = Q K^T tile (64x64), 4x4 per thread
        float s[4][4] = {};
        #pragma unroll
        for (int d = 0; d < 32; d++) {
            float4 A = *(float4*)&Qt[d][ty * 4];
            float4 B = *(float4*)&Kt[d][tx * 4];
            float a[4] = {A.x, A.y, A.z, A.w};
            float bb[4] = {B.x, B.y, B.z, B.w};
            #pragma unroll
            for (int i = 0; i < 4; i++)
                #pragma unroll
                for (int j = 0; j < 4; j++)
                    s[i][j] = fmaf(a[i], bb[j], s[i][j]);
        }

        // Online softmax (row reductions across the 16 tx-lanes of each half-warp)
        #pragma unroll
        for (int i = 0; i < 4; i++) {
            float rm = fmaxf(fmaxf(s[i][0], s[i][1]), fmaxf(s[i][2], s[i][3]));
            rm = fmaxf(rm, __shfl_xor_sync(0xffffffffu, rm, 1));
            rm = fmaxf(rm, __shfl_xor_sync(0xffffffffu, rm, 2));
            rm = fmaxf(rm, __shfl_xor_sync(0xffffffffu, rm, 4));
            rm = fmaxf(rm, __shfl_xor_sync(0xffffffffu, rm, 8));
            float mn = fmaxf(m[i], rm);
            float corr = __expf(m[i] - mn);
            float p0v = __expf(s[i][0] - mn);
            float p1v = __expf(s[i][1] - mn);
            float p2v = __expf(s[i][2] - mn);
            float p3v = __expf(s[i][3] - mn);
            float rs = p0v + p1v + p2v + p3v;
            rs += __shfl_xor_sync(0xffffffffu, rs, 1);
            rs += __shfl_xor_sync(0xffffffffu, rs, 2);
            rs += __shfl_xor_sync(0xffffffffu, rs, 4);
            rs += __shfl_xor_sync(0xffffffffu, rs, 8);
            l[i] = l[i] * corr + rs;
            O[i][0] *= corr; O[i][1] *= corr;
            m[i] = mn;
            float4 pv = make_float4(p0v, p1v, p2v, p3v);
            *(float4*)&Ps[ty * 4 + i][tx * 4] = pv;
        }
        __syncthreads();

        // O += P V  (per thread: 4 rows x 2 dims)
        #pragma unroll
        for (int k4 = 0; k4 < 16; k4++) {
            float Pa[4][4];
            #pragma unroll
            for (int i = 0; i < 4; i++) {
                float4 t = *(float4*)&Ps[ty * 4 + i][k4 * 4];
                Pa[i][0] = t.x; Pa[i][1] = t.y; Pa[i][2] = t.z; Pa[i][3] = t.w;
            }
            #pragma unroll
            for (int kk = 0; kk < 4; kk++) {
                float2 v = *(float2*)&Vs[k4 * 4 + kk][tx * 2];
                #pragma unroll
                for (int i = 0; i < 4; i++) {
                    O[i][0] = fmaf(Pa[i][kk], v.x, O[i][0]);
                    O[i][1] = fmaf(Pa[i][kk], v.y, O[i][1]);
                }
            }
        }
    }

    // Epilogue: normalize and write [n][h*32+dim][p]
    #pragma unroll
    for (int i = 0; i < 4; i++) {
        float inv = 1.f / l[i];
        int p = q0 + ty * 4 + i;
        g_o[((size_t)n * CH + h * DH + tx * 2 + 0) * HW + p] = O[i][0] * inv;
        g_o[((size_t)n * CH + h * DH + tx * 2 + 1) * HW + p] = O[i][1] * inv;
    }
}

// ---------------------------------------------------------------------------
// Out projection: pj[n][d][p] = sum_c o[n][c][p] * w_out[c][d] + b_out[d]
// ---------------------------------------------------------------------------
__global__ __launch_bounds__(256) void proj_kernel(const float* __restrict__ w,
                                                   const float* __restrict__ bias) {
    int p0 = blockIdx.x * 64, d0 = blockIdx.y * 64, n = blockIdx.z;
    int tid = threadIdx.x, ty = tid >> 4, tx = tid & 15;
    __shared__ float Ws[16][64];
    __shared__ float Xs[16][64];
    float acc[4][4] = {};
    const float* xb = g_o + (size_t)n * CH * HW;

    int lr = tid >> 4, lc = (tid & 15) << 2;
    for (int c0 = 0; c0 < CH; c0 += 16) {
        *(float4*)&Ws[lr][lc] = *(const float4*)&w [(size_t)(c0 + lr) * 128 + d0 + lc];
        *(float4*)&Xs[lr][lc] = *(const float4*)&xb[(size_t)(c0 + lr) * HW  + p0 + lc];
        __syncthreads();
        #pragma unroll
        for (int k = 0; k < 16; k++) {
            float4 A = *(float4*)&Ws[k][ty * 4];
            float4 B = *(float4*)&Xs[k][tx * 4];
            float a[4] = {A.x, A.y, A.z, A.w};
            float bb[4] = {B.x, B.y, B.z, B.w};
            #pragma unroll
            for (int i = 0; i < 4; i++)
                #pragma unroll
                for (int j = 0; j < 4; j++)
                    acc[i][j] = fmaf(a[i], bb[j], acc[i][j]);
        }
        __syncthreads();
    }
    #pragma unroll
    for (int i = 0; i < 4; i++) {
        int d = d0 + ty * 4 + i;
        float bv = bias[d];
        #pragma unroll
        for (int j = 0; j < 4; j++) {
            int p = p0 + tx * 4 + j;
            g_pj[((size_t)n * CH + d) * HW + p] = acc[i][j] + bv;
        }
    }
}

// ---------------------------------------------------------------------------
// GroupNorm 2 + residual: out = xn + gn2(pj)
// ---------------------------------------------------------------------------
__global__ __launch_bounds__(512) void gn2_kernel(const float* __restrict__ sc,
                                                  const float* __restrict__ off,
                                                  float* __restrict__ out) {
    int b = blockIdx.x;
    int n = b >> 4, g = b & 15;
    const int M = CPG * HW;
    size_t base = ((size_t)n * CH + (size_t)g * CPG) * HW;

    float s = 0.f, q = 0.f;
    for (int i = threadIdx.x; i < M; i += 512) {
        float v = g_pj[base + i]; s += v; q += v * v;
    }
    __shared__ float ss[512], sq[512];
    ss[threadIdx.x] = s; sq[threadIdx.x] = q;
    __syncthreads();
    for (int st = 256; st > 0; st >>= 1) {
        if (threadIdx.x < st) {
            ss[threadIdx.x] += ss[threadIdx.x + st];
            sq[threadIdx.x] += sq[threadIdx.x + st];
        }
        __syncthreads();
    }
    float mu  = ss[0] / (float)M;
    float var = sq[0] / (float)M - mu * mu;
    float r   = rsqrtf(var + EPSF);

    for (int i = threadIdx.x; i < M; i += 512) {
        int c = g * CPG + (i >> 12);
        out[base + i] = g_xn[base + i] + (g_pj[base + i] - mu) * r * sc[c] + off[c];
    }
}

// ---------------------------------------------------------------------------
extern "C" void kernel_launch(void* const* d_in, const int* in_sizes, int n_in,
                              void* d_out, int out_size) {
    const float* x      = (const float*)d_in[0];
    const float* w_qkv  = (const float*)d_in[1];
    const float* b_qkv  = (const float*)d_in[2];
    const float* w_out  = (const float*)d_in[3];
    const float* b_out  = (const float*)d_in[4];
    const float* gn1_s  = (const float*)d_in[5];
    const float* gn1_o  = (const float*)d_in[6];
    const float* gn2_s  = (const float*)d_in[7];
    const float* gn2_o  = (const float*)d_in[8];
    float* out = (float*)d_out;

    gn1_kernel<<<32, 512>>>(x, gn1_s, gn1_o);
    qkv_kernel<<<dim3(HW / 64, 6, NB), 256>>>(w_qkv, b_qkv);
    attn_kernel<<<dim3(HW / 64, NB * NHD), 256>>>();
    proj_kernel<<<dim3(HW / 64, 2, NB), 256>>>(w_out, b_out);
    gn2_kernel<<<32, 512>>>(gn2_s, gn2_o, out);
}